// round 1
// baseline (speedup 1.0000x reference)
#include <cuda_runtime.h>

#define NN   100000
#define NE   1600000
#define DD   128
#define NG   64
#define NCLS 16
#define SBS  512
#define SNB  ((NN + SBS - 1) / SBS)   // 196

// ---------------- device scratch (no allocs allowed) ----------------
__device__ __align__(16) float d_neigh[NN * DD];
__device__ __align__(16) float d_x1[NN * DD];
__device__ __align__(16) float d_x2[NN * DD];
__device__ int d_deg[NN];
__device__ int d_off[NN + 1];
__device__ int d_cursor[NN];
__device__ int d_sorted[NE];
__device__ int d_gcnt[NG];
__device__ int d_bsum[SNB];

// ---------------- f32x2 packed-FMA helpers (FFMA2) ----------------
__device__ __forceinline__ unsigned long long dup2(float x) {
    unsigned int u = __float_as_uint(x);
    unsigned long long r;
    asm("mov.b64 %0, {%1, %1};" : "=l"(r) : "r"(u));
    return r;
}
__device__ __forceinline__ unsigned long long fma2(unsigned long long a,
                                                   unsigned long long b,
                                                   unsigned long long c) {
    unsigned long long d;
    asm("fma.rn.f32x2 %0, %1, %2, %3;" : "=l"(d) : "l"(a), "l"(b), "l"(c));
    return d;
}
__device__ __forceinline__ float2 unpack2(unsigned long long v) {
    unsigned int lo, hi;
    asm("mov.b64 {%0, %1}, %2;" : "=r"(lo), "=r"(hi) : "l"(v));
    float2 f;
    f.x = __uint_as_float(lo);
    f.y = __uint_as_float(hi);
    return f;
}

// ---------------- small kernels: degree count + counting sort ----------------
__global__ void k_zero() {
    int i = blockIdx.x * blockDim.x + threadIdx.x;
    if (i < NN) d_deg[i] = 0;
    if (i < NG) d_gcnt[i] = 0;
}

__global__ void k_count(const int* __restrict__ dst, const int* __restrict__ gid) {
    int i = blockIdx.x * blockDim.x + threadIdx.x;
    if (i < NE) atomicAdd(&d_deg[dst[i]], 1);
    if (i < NN) atomicAdd(&d_gcnt[gid[i]], 1);
}

__global__ void k_scan1() {
    __shared__ int sm[SBS];
    int t = threadIdx.x;
    int i = blockIdx.x * SBS + t;
    int v = (i < NN) ? d_deg[i] : 0;
    sm[t] = v;
    __syncthreads();
    for (int s = 1; s < SBS; s <<= 1) {
        int add = (t >= s) ? sm[t - s] : 0;
        __syncthreads();
        sm[t] += add;
        __syncthreads();
    }
    if (i < NN) d_off[i] = sm[t] - v;             // local exclusive
    if (t == SBS - 1) d_bsum[blockIdx.x] = sm[t]; // block total
}

__global__ void k_scan2() {
    __shared__ int sm[256];
    int t = threadIdx.x;
    int v = (t < SNB) ? d_bsum[t] : 0;
    sm[t] = v;
    __syncthreads();
    for (int s = 1; s < 256; s <<= 1) {
        int add = (t >= s) ? sm[t - s] : 0;
        __syncthreads();
        sm[t] += add;
        __syncthreads();
    }
    if (t < SNB) d_bsum[t] = sm[t] - v;           // exclusive block prefix
}

__global__ void k_scan3() {
    int i = blockIdx.x * blockDim.x + threadIdx.x;
    if (i < NN) {
        int v = d_off[i] + d_bsum[i / SBS];
        d_off[i] = v;
        d_cursor[i] = v;
    }
    if (i == 0) d_off[NN] = NE;
}

__global__ void k_scatter(const int* __restrict__ src, const int* __restrict__ dst) {
    int e = blockIdx.x * blockDim.x + threadIdx.x;
    if (e < NE) {
        int p = atomicAdd(&d_cursor[dst[e]], 1);
        d_sorted[p] = src[e];
    }
}

// ---------------- aggregation: one warp per node, 512B row gather ----------------
__global__ void k_agg(const float4* __restrict__ feat) {
    int warp = (blockIdx.x * blockDim.x + threadIdx.x) >> 5;
    int lane = threadIdx.x & 31;
    if (warp >= NN) return;
    int e0 = d_off[warp];
    int e1 = d_off[warp + 1];
    float4 acc = make_float4(0.f, 0.f, 0.f, 0.f);
#pragma unroll 4
    for (int e = e0; e < e1; e++) {
        int s = d_sorted[e];                 // uniform across warp
        float4 v = feat[s * 32 + lane];
        acc.x += v.x; acc.y += v.y; acc.z += v.z; acc.w += v.w;
    }
    float inv = 1.0f / fmaxf((float)(e1 - e0), 1.0f);
    acc.x *= inv; acc.y *= inv; acc.z *= inv; acc.w *= inv;
    ((float4*)d_neigh)[warp * 32 + lane] = acc;
}

// ---------------- fused dual GEMM: out = act(As@Ws + An@Wn + b) ----------------
// Tiles: 128 rows x 128 cols per block, K chunked by 16. f32x2 packed FMAs.
#define BK 16
__global__ void __launch_bounds__(256, 2) k_gemm(
    const float* __restrict__ As, const float* __restrict__ An,
    const float* __restrict__ Ws, const float* __restrict__ Wn,
    const float* __restrict__ bias, float* __restrict__ outp, int relu)
{
    __shared__ float sA[2][BK][132];   // [mat][k][m], padded
    __shared__ float sW[2][BK][DD];    // [mat][k][j]

    const int tid = threadIdx.x;
    const int ty = tid >> 4;    // node group 0..15 (8 nodes each)
    const int tx = tid & 15;    // col group 0..15 (8 cols each)
    const int m_base = blockIdx.x * 128;

    unsigned long long acc[8][4];
#pragma unroll
    for (int i = 0; i < 8; i++)
#pragma unroll
        for (int p = 0; p < 4; p++) acc[i][p] = 0ull;

    const float4* A4[2] = { (const float4*)As, (const float4*)An };
    const float4* W4[2] = { (const float4*)Ws, (const float4*)Wn };

#pragma unroll 1
    for (int kc = 0; kc < DD / BK; kc++) {
        // stage A tiles (transposed to [k][m]) — 2 passes per matrix
#pragma unroll
        for (int mat = 0; mat < 2; mat++) {
#pragma unroll
            for (int pass = 0; pass < 2; pass++) {
                int i = pass * 256 + tid;
                int row = i >> 2;          // 0..127
                int quad = i & 3;          // float4 index within BK chunk
                int m = m_base + row;
                float4 v = make_float4(0.f, 0.f, 0.f, 0.f);
                if (m < NN) v = A4[mat][m * 32 + kc * 4 + quad];
                sA[mat][quad * 4 + 0][row] = v.x;
                sA[mat][quad * 4 + 1][row] = v.y;
                sA[mat][quad * 4 + 2][row] = v.z;
                sA[mat][quad * 4 + 3][row] = v.w;
            }
            // stage W tile
#pragma unroll
            for (int pass = 0; pass < 2; pass++) {
                int i = pass * 256 + tid;
                int krow = i >> 5;         // 0..15
                int q = i & 31;            // float4 within 128-col row
                float4 v = W4[mat][(kc * BK + krow) * 32 + q];
                *(float4*)&sW[mat][krow][q * 4] = v;
            }
        }
        __syncthreads();

#pragma unroll 2
        for (int k = 0; k < BK; k++) {
            float4 as0 = *(const float4*)&sA[0][k][ty * 8];
            float4 as1 = *(const float4*)&sA[0][k][ty * 8 + 4];
            float4 an0 = *(const float4*)&sA[1][k][ty * 8];
            float4 an1 = *(const float4*)&sA[1][k][ty * 8 + 4];
            ulonglong2 w0 = *(const ulonglong2*)&sW[0][k][tx * 8];
            ulonglong2 w1 = *(const ulonglong2*)&sW[0][k][tx * 8 + 4];
            ulonglong2 u0 = *(const ulonglong2*)&sW[1][k][tx * 8];
            ulonglong2 u1 = *(const ulonglong2*)&sW[1][k][tx * 8 + 4];
            unsigned long long wsp[4] = { w0.x, w0.y, w1.x, w1.y };
            unsigned long long wnp[4] = { u0.x, u0.y, u1.x, u1.y };
            float aS[8] = { as0.x, as0.y, as0.z, as0.w, as1.x, as1.y, as1.z, as1.w };
            float aN[8] = { an0.x, an0.y, an0.z, an0.w, an1.x, an1.y, an1.z, an1.w };
#pragma unroll
            for (int i = 0; i < 8; i++) {
                unsigned long long dS = dup2(aS[i]);
                unsigned long long dN = dup2(aN[i]);
#pragma unroll
                for (int p = 0; p < 4; p++) {
                    acc[i][p] = fma2(dS, wsp[p], acc[i][p]);
                    acc[i][p] = fma2(dN, wnp[p], acc[i][p]);
                }
            }
        }
        __syncthreads();
    }

    // epilogue
    float bv[8];
#pragma unroll
    for (int c = 0; c < 8; c++) bv[c] = bias[tx * 8 + c];

#pragma unroll
    for (int i = 0; i < 8; i++) {
        int m = m_base + ty * 8 + i;
        if (m >= NN) continue;
        float o[8];
#pragma unroll
        for (int p = 0; p < 4; p++) {
            float2 f = unpack2(acc[i][p]);
            o[2 * p]     = f.x + bv[2 * p];
            o[2 * p + 1] = f.y + bv[2 * p + 1];
        }
        if (relu) {
#pragma unroll
            for (int c = 0; c < 8; c++) o[c] = fmaxf(o[c], 0.f);
        }
        float4* dst4 = (float4*)&outp[m * DD + tx * 8];
        dst4[0] = make_float4(o[0], o[1], o[2], o[3]);
        dst4[1] = make_float4(o[4], o[5], o[6], o[7]);
    }
}

// ---------------- graph mean pooling + classifier ----------------
__global__ void k_pool(const float* __restrict__ x2, const float* __restrict__ Wc,
                       const float* __restrict__ bc, float* __restrict__ out)
{
    __shared__ float sacc[256];
    __shared__ float smean[DD];
    int g = blockIdx.x;
    int t = threadIdx.x;

    int start = 0;
    for (int i = 0; i < NG; i++) {
        int c = d_gcnt[i];
        if (i < g) start += c;
    }
    int cnt = d_gcnt[g];

    int col = t & 127;
    int half = t >> 7;
    float acc = 0.f;
    for (int r = start + half; r < start + cnt; r += 2)
        acc += x2[r * DD + col];
    sacc[t] = acc;
    __syncthreads();
    if (t < DD)
        smean[t] = (sacc[t] + sacc[t + 128]) / fmaxf((float)cnt, 1.0f);
    __syncthreads();
    if (t < NCLS) {
        float o = bc[t];
#pragma unroll 4
        for (int k = 0; k < DD; k++) o += smean[k] * Wc[k * NCLS + t];
        out[g * NCLS + t] = o;
    }
}

// ---------------- launch ----------------
extern "C" void kernel_launch(void* const* d_in, const int* in_sizes, int n_in,
                              void* d_out, int out_size)
{
    const float* h   = (const float*)d_in[0];
    const int*   src = (const int*)d_in[1];
    const int*   dst = (const int*)d_in[2];
    const int*   gid = (const int*)d_in[3];
    // hedge: num_graphs may or may not be materialized as a size-1 buffer
    int wb = (in_sizes[4] == 1) ? 5 : 4;
    const float* W1s = (const float*)d_in[wb + 0];
    const float* W1n = (const float*)d_in[wb + 1];
    const float* b1  = (const float*)d_in[wb + 2];
    const float* W2s = (const float*)d_in[wb + 3];
    const float* W2n = (const float*)d_in[wb + 4];
    const float* b2  = (const float*)d_in[wb + 5];
    const float* Wc  = (const float*)d_in[wb + 6];
    const float* bc  = (const float*)d_in[wb + 7];
    float* out = (float*)d_out;

    void *pn = nullptr, *px1 = nullptr, *px2 = nullptr;
    cudaGetSymbolAddress(&pn, d_neigh);
    cudaGetSymbolAddress(&px1, d_x1);
    cudaGetSymbolAddress(&px2, d_x2);
    float* neigh = (float*)pn;
    float* x1 = (float*)px1;
    float* x2 = (float*)px2;

    // build CSR by dst (counting sort) — shared by both layers
    k_zero<<<(NN + 255) / 256, 256>>>();
    k_count<<<(NE + 255) / 256, 256>>>(dst, gid);
    k_scan1<<<SNB, SBS>>>();
    k_scan2<<<1, 256>>>();
    k_scan3<<<(NN + 255) / 256, 256>>>();
    k_scatter<<<(NE + 255) / 256, 256>>>(src, dst);

    // layer 1
    k_agg<<<NN / 8, 256>>>((const float4*)h);
    k_gemm<<<(NN + 127) / 128, 256>>>(h, neigh, W1s, W1n, b1, x1, 1);

    // layer 2
    k_agg<<<NN / 8, 256>>>((const float4*)x1);
    k_gemm<<<(NN + 127) / 128, 256>>>(x1, neigh, W2s, W2n, b2, x2, 0);

    // pooling + classifier
    k_pool<<<NG, 256>>>(x2, Wc, bc, out);
}

// round 5
// speedup vs baseline: 1.8164x; 1.8164x over previous
#include <cuda_runtime.h>
#include <cuda_fp16.h>
#include <cstdint>

#define NN   100000
#define NE   1600000
#define DD   128
#define NG   64
#define NCLS 16
#define SBS  512
#define SNB  ((NN + SBS - 1) / SBS)   // 196

// ---------------- device scratch (no allocs allowed) ----------------
__device__ __align__(16) __half d_hb[NN * DD];      // h in fp16
__device__ __align__(16) __half d_neighb[NN * DD];  // aggregated (fp16)
__device__ __align__(16) __half d_x1b[NN * DD];
__device__ __align__(16) __half d_x2b[NN * DD];
__device__ __align__(16) __half d_wimg[2][128 * 256]; // [layer][n][k0..255]
__device__ int d_deg[NN];
__device__ int d_off[NN + 1];
__device__ int d_cursor[NN];
__device__ int d_sorted[NE];
__device__ int d_gcnt[NG];
__device__ int d_bsum[SNB];

// ---------------- PTX helpers ----------------
__device__ __forceinline__ uint32_t smem_to_u32(const void* p) {
    uint32_t a;
    asm("{ .reg .u64 t; cvta.to.shared.u64 t, %1; cvt.u32.u64 %0, t; }" : "=r"(a) : "l"(p));
    return a;
}
__device__ __forceinline__ void ldsm4(uint32_t* r, uint32_t addr) {
    asm volatile("ldmatrix.sync.aligned.m8n8.x4.shared.b16 {%0,%1,%2,%3}, [%4];"
                 : "=r"(r[0]), "=r"(r[1]), "=r"(r[2]), "=r"(r[3]) : "r"(addr));
}
__device__ __forceinline__ void mma_f16(float* c, const uint32_t* a, const uint32_t* b) {
    asm volatile(
        "mma.sync.aligned.m16n8k16.row.col.f32.f16.f16.f32 "
        "{%0,%1,%2,%3},{%4,%5,%6,%7},{%8,%9},{%0,%1,%2,%3};"
        : "+f"(c[0]), "+f"(c[1]), "+f"(c[2]), "+f"(c[3])
        : "r"(a[0]), "r"(a[1]), "r"(a[2]), "r"(a[3]), "r"(b[0]), "r"(b[1]));
}

// ---------------- conversions ----------------
__global__ void k_cvth(const float4* __restrict__ in, uint4* __restrict__ out) {
    int i = blockIdx.x * blockDim.x + threadIdx.x;
    if (i >= NN * DD / 8) return;
    float4 a = in[2 * i], b = in[2 * i + 1];
    __half2 p0 = __floats2half2_rn(a.x, a.y);
    __half2 p1 = __floats2half2_rn(a.z, a.w);
    __half2 p2 = __floats2half2_rn(b.x, b.y);
    __half2 p3 = __floats2half2_rn(b.z, b.w);
    uint4 o;
    o.x = *(uint32_t*)&p0; o.y = *(uint32_t*)&p1;
    o.z = *(uint32_t*)&p2; o.w = *(uint32_t*)&p3;
    out[i] = o;
}

// weights [K=128,N=128] fp32 (self & neigh) -> combined [N=128][K=256] fp16
__global__ void k_cvtw(const float* __restrict__ Ws, const float* __restrict__ Wn, int layer) {
    int i = blockIdx.x * blockDim.x + threadIdx.x;
    if (i >= 128 * 128) return;
    int k = i >> 7, n = i & 127;
    d_wimg[layer][n * 256 + k]       = __float2half_rn(Ws[k * 128 + n]);
    d_wimg[layer][n * 256 + 128 + k] = __float2half_rn(Wn[k * 128 + n]);
}

// ---------------- CSR build (counting sort by dst) ----------------
__global__ void k_zero() {
    int i = blockIdx.x * blockDim.x + threadIdx.x;
    if (i < NN) d_deg[i] = 0;
    if (i < NG) d_gcnt[i] = 0;
}
__global__ void k_count(const int* __restrict__ dst, const int* __restrict__ gid) {
    int i = blockIdx.x * blockDim.x + threadIdx.x;
    if (i < NE) atomicAdd(&d_deg[dst[i]], 1);
    if (i < NN) atomicAdd(&d_gcnt[gid[i]], 1);
}
__global__ void k_scan1() {
    __shared__ int sm[SBS];
    int t = threadIdx.x;
    int i = blockIdx.x * SBS + t;
    int v = (i < NN) ? d_deg[i] : 0;
    sm[t] = v;
    __syncthreads();
    for (int s = 1; s < SBS; s <<= 1) {
        int add = (t >= s) ? sm[t - s] : 0;
        __syncthreads();
        sm[t] += add;
        __syncthreads();
    }
    if (i < NN) d_off[i] = sm[t] - v;
    if (t == SBS - 1) d_bsum[blockIdx.x] = sm[t];
}
__global__ void k_scan2() {
    __shared__ int sm[256];
    int t = threadIdx.x;
    int v = (t < SNB) ? d_bsum[t] : 0;
    sm[t] = v;
    __syncthreads();
    for (int s = 1; s < 256; s <<= 1) {
        int add = (t >= s) ? sm[t - s] : 0;
        __syncthreads();
        sm[t] += add;
        __syncthreads();
    }
    if (t < SNB) d_bsum[t] = sm[t] - v;
}
__global__ void k_scan3() {
    int i = blockIdx.x * blockDim.x + threadIdx.x;
    if (i < NN) {
        int v = d_off[i] + d_bsum[i / SBS];
        d_off[i] = v;
        d_cursor[i] = v;
    }
    if (i == 0) d_off[NN] = NE;
}
__global__ void k_scatter(const int* __restrict__ src, const int* __restrict__ dst) {
    int e = blockIdx.x * blockDim.x + threadIdx.x;
    if (e < NE) {
        int p = atomicAdd(&d_cursor[dst[e]], 1);
        d_sorted[p] = src[e];
    }
}

// ---------------- aggregation (fp16 gather, fp32 accumulate) ----------------
__global__ void k_agg(const uint2* __restrict__ feat) {
    int warp = (blockIdx.x * blockDim.x + threadIdx.x) >> 5;
    int lane = threadIdx.x & 31;
    if (warp >= NN) return;
    int e0 = d_off[warp];
    int e1 = d_off[warp + 1];
    float ax = 0.f, ay = 0.f, az = 0.f, aw = 0.f;
#pragma unroll 4
    for (int e = e0; e < e1; e++) {
        int s = d_sorted[e];
        uint2 v = feat[s * 32 + lane];
        float2 p0 = __half22float2(*(__half2*)&v.x);
        float2 p1 = __half22float2(*(__half2*)&v.y);
        ax += p0.x; ay += p0.y;
        az += p1.x; aw += p1.y;
    }
    float inv = 1.0f / fmaxf((float)(e1 - e0), 1.0f);
    __half2 q0 = __floats2half2_rn(ax * inv, ay * inv);
    __half2 q1 = __floats2half2_rn(az * inv, aw * inv);
    uint2 o; o.x = *(uint32_t*)&q0; o.y = *(uint32_t*)&q1;
    ((uint2*)d_neighb)[warp * 32 + lane] = o;
}

// ---------------- fused dual GEMM via mma.sync (HMMA fp16) ----------------
// D[128m,128n] = [As|An](128x256) @ Bimg(128n x 256k)^T, K=256, one shot.
#define ROWB 528                         // padded row stride in bytes (264 halves)
#define SMA  (128 * ROWB)                // 67584
#define SM_TOT (2 * SMA)                 // 135168

__global__ void __launch_bounds__(256, 1) k_gemm_mma(
    const uint4* __restrict__ Aself, const uint4* __restrict__ Aneigh,
    const uint4* __restrict__ Bimg, const float* __restrict__ bias,
    uint32_t* __restrict__ outp, int relu)
{
    extern __shared__ __align__(16) char smem[];
    char* sA = smem;
    char* sB = smem + SMA;
    const int tid = threadIdx.x;
    const int wid = tid >> 5;
    const int lane = tid & 31;
    const int m_base = blockIdx.x * 128;

    // stage A: rows = nodes, cols 0-127 self / 128-255 neigh (fp16)
#pragma unroll
    for (int it = 0; it < 16; it++) {
        int idx = it * 256 + tid;           // 0..4095
        int row = idx >> 5, q = idx & 31;   // q: uint4 within 256-half row
        int m = m_base + row;
        uint4 v = make_uint4(0, 0, 0, 0);
        if (m < NN) v = (q < 16) ? Aself[m * 16 + q] : Aneigh[m * 16 + (q - 16)];
        *(uint4*)(sA + row * ROWB + q * 16) = v;
    }
    // stage B: [n][k] fp16, flat from global
#pragma unroll
    for (int it = 0; it < 16; it++) {
        int idx = it * 256 + tid;
        int row = idx >> 5, q = idx & 31;
        *(uint4*)(sB + row * ROWB + q * 16) = Bimg[idx];
    }
    __syncthreads();

    const int warpM = wid >> 1;   // 0..3 -> 32-row band
    const int warpN = wid & 1;    // 0..1 -> 64-col band

    float acc[2][8][4];
#pragma unroll
    for (int i = 0; i < 2; i++)
#pragma unroll
        for (int j = 0; j < 8; j++)
#pragma unroll
            for (int p = 0; p < 4; p++) acc[i][j][p] = 0.f;

    uint32_t aBase = smem_to_u32(sA) + (warpM * 32 + (lane & 15)) * ROWB + (lane >> 4) * 16;
    uint32_t bBase = smem_to_u32(sB) +
                     (warpN * 64 + (lane & 7) + ((lane >> 4) & 1) * 8) * ROWB +
                     ((lane >> 3) & 1) * 16;

#pragma unroll
    for (int ks = 0; ks < 16; ks++) {
        uint32_t a[2][4];
        ldsm4(a[0], aBase + ks * 32);
        ldsm4(a[1], aBase + 16 * ROWB + ks * 32);
        uint32_t b[4][4];
#pragma unroll
        for (int nb = 0; nb < 4; nb++)
            ldsm4(b[nb], bBase + nb * 16 * ROWB + ks * 32);
#pragma unroll
        for (int mi = 0; mi < 2; mi++)
#pragma unroll
            for (int nb = 0; nb < 4; nb++) {
                mma_f16(acc[mi][2 * nb],     a[mi], &b[nb][0]);
                mma_f16(acc[mi][2 * nb + 1], a[mi], &b[nb][2]);
            }
    }

    // epilogue: bias + optional relu, fp16 pairs to global
    const int qcol = 2 * (lane & 3);
    const int qrow = lane >> 2;
#pragma unroll
    for (int ni = 0; ni < 8; ni++) {
        int n = warpN * 64 + ni * 8 + qcol;
        float b0 = bias[n], b1 = bias[n + 1];
#pragma unroll
        for (int mi = 0; mi < 2; mi++) {
            int m0 = m_base + warpM * 32 + mi * 16 + qrow;
#pragma unroll
            for (int half = 0; half < 2; half++) {
                int m = m0 + half * 8;
                if (m >= NN) continue;
                float f0 = acc[mi][ni][2 * half]     + b0;
                float f1 = acc[mi][ni][2 * half + 1] + b1;
                if (relu) { f0 = fmaxf(f0, 0.f); f1 = fmaxf(f1, 0.f); }
                __half2 pk = __floats2half2_rn(f0, f1);
                outp[m * 64 + n / 2] = *(uint32_t*)&pk;
            }
        }
    }
}

// ---------------- graph mean pooling + classifier ----------------
__global__ void k_pool(const __half* __restrict__ x2, const float* __restrict__ Wc,
                       const float* __restrict__ bc, float* __restrict__ out)
{
    __shared__ float sacc[256];
    __shared__ float smean[DD];
    int g = blockIdx.x;
    int t = threadIdx.x;

    int start = 0;
    for (int i = 0; i < NG; i++) {
        int c = d_gcnt[i];
        if (i < g) start += c;
    }
    int cnt = d_gcnt[g];

    int col = t & 127;
    int half = t >> 7;
    float acc = 0.f;
    for (int r = start + half; r < start + cnt; r += 2)
        acc += __half2float(x2[(size_t)r * DD + col]);
    sacc[t] = acc;
    __syncthreads();
    if (t < DD)
        smean[t] = (sacc[t] + sacc[t + 128]) / fmaxf((float)cnt, 1.0f);
    __syncthreads();
    if (t < NCLS) {
        float o = bc[t];
#pragma unroll 4
        for (int k = 0; k < DD; k++) o += smean[k] * Wc[k * NCLS + t];
        out[g * NCLS + t] = o;
    }
}

// ---------------- launch ----------------
extern "C" void kernel_launch(void* const* d_in, const int* in_sizes, int n_in,
                              void* d_out, int out_size)
{
    const float* h   = (const float*)d_in[0];
    const int*   src = (const int*)d_in[1];
    const int*   dst = (const int*)d_in[2];
    const int*   gid = (const int*)d_in[3];
    int wb = (in_sizes[4] == 1) ? 5 : 4;
    const float* W1s = (const float*)d_in[wb + 0];
    const float* W1n = (const float*)d_in[wb + 1];
    const float* b1  = (const float*)d_in[wb + 2];
    const float* W2s = (const float*)d_in[wb + 3];
    const float* W2n = (const float*)d_in[wb + 4];
    const float* b2  = (const float*)d_in[wb + 5];
    const float* Wc  = (const float*)d_in[wb + 6];
    const float* bc  = (const float*)d_in[wb + 7];
    float* out = (float*)d_out;

    void *phb, *pnb, *px1, *px2, *pw;
    cudaGetSymbolAddress(&phb, d_hb);
    cudaGetSymbolAddress(&pnb, d_neighb);
    cudaGetSymbolAddress(&px1, d_x1b);
    cudaGetSymbolAddress(&px2, d_x2b);
    cudaGetSymbolAddress(&pw, d_wimg);
    __half* hb = (__half*)phb;
    __half* nb = (__half*)pnb;
    __half* x1 = (__half*)px1;
    __half* x2 = (__half*)px2;
    const uint4* wimg = (const uint4*)pw;

    static int smem_set = 0;
    if (!smem_set) {
        cudaFuncSetAttribute(k_gemm_mma, cudaFuncAttributeMaxDynamicSharedMemorySize, SM_TOT);
        smem_set = 1;
    }

    // conversions
    k_cvth<<<(NN * DD / 8 + 255) / 256, 256>>>((const float4*)h, (uint4*)hb);
    k_cvtw<<<64, 256>>>(W1s, W1n, 0);
    k_cvtw<<<64, 256>>>(W2s, W2n, 1);

    // CSR by dst (counting sort)
    k_zero<<<(NN + 255) / 256, 256>>>();
    k_count<<<(NE + 255) / 256, 256>>>(dst, gid);
    k_scan1<<<SNB, SBS>>>();
    k_scan2<<<1, 256>>>();
    k_scan3<<<(NN + 255) / 256, 256>>>();
    k_scatter<<<(NE + 255) / 256, 256>>>(src, dst);

    const int GB = (NN + 127) / 128;   // 782 tiles
    // each weight image = 128*256 fp16 = 65536 B = 4096 uint4
    const uint4* B1 = wimg;
    const uint4* B2 = wimg + 4096;

    // layer 1
    k_agg<<<NN / 8, 256>>>((const uint2*)hb);
    k_gemm_mma<<<GB, 256, SM_TOT>>>((const uint4*)hb, (const uint4*)nb, B1, b1,
                                    (uint32_t*)x1, 1);
    // layer 2
    k_agg<<<NN / 8, 256>>>((const uint2*)x1);
    k_gemm_mma<<<GB, 256, SM_TOT>>>((const uint4*)x1, (const uint4*)nb, B2, b2,
                                    (uint32_t*)x2, 0);

    // pooling + classifier
    k_pool<<<NG, 256>>>(x2, Wc, bc, out);
}

// round 6
// speedup vs baseline: 1.8617x; 1.0249x over previous
#include <cuda_runtime.h>
#include <cuda_fp16.h>
#include <cstdint>

#define NN   100000
#define NE   1600000
#define DD   128
#define NG   64
#define NCLS 16
#define SBS  512
#define SNB  ((NN + SBS - 1) / SBS)   // 196

// ---------------- device scratch (no allocs allowed) ----------------
__device__ __align__(16) __half d_hb[NN * DD];      // h in fp16
__device__ __align__(16) __half d_neighb[NN * DD];  // aggregated (fp16)
__device__ __align__(16) __half d_x1b[NN * DD];
__device__ __align__(16) __half d_x2b[NN * DD];
__device__ __align__(16) __half d_wimg[2][128 * 256]; // [layer][n][k0..255]
__device__ float d_gsum[NG * DD];
__device__ int d_deg[NN];
__device__ int d_off[NN + 1];
__device__ int d_cursor[NN];
__device__ int d_sorted[NE];
__device__ int d_gcnt[NG];
__device__ int d_bsum[SNB];

// ---------------- PTX helpers ----------------
__device__ __forceinline__ uint32_t smem_to_u32(const void* p) {
    uint32_t a;
    asm("{ .reg .u64 t; cvta.to.shared.u64 t, %1; cvt.u32.u64 %0, t; }" : "=r"(a) : "l"(p));
    return a;
}
__device__ __forceinline__ void ldsm4(uint32_t* r, uint32_t addr) {
    asm volatile("ldmatrix.sync.aligned.m8n8.x4.shared.b16 {%0,%1,%2,%3}, [%4];"
                 : "=r"(r[0]), "=r"(r[1]), "=r"(r[2]), "=r"(r[3]) : "r"(addr));
}
__device__ __forceinline__ void mma_f16(float* c, const uint32_t* a, const uint32_t* b) {
    asm volatile(
        "mma.sync.aligned.m16n8k16.row.col.f32.f16.f16.f32 "
        "{%0,%1,%2,%3},{%4,%5,%6,%7},{%8,%9},{%0,%1,%2,%3};"
        : "+f"(c[0]), "+f"(c[1]), "+f"(c[2]), "+f"(c[3])
        : "r"(a[0]), "r"(a[1]), "r"(a[2]), "r"(a[3]), "r"(b[0]), "r"(b[1]));
}

// ---------------- conversions (+ fused zeroing of counters) ----------------
__global__ void k_cvth(const float4* __restrict__ in, uint4* __restrict__ out) {
    int i = blockIdx.x * blockDim.x + threadIdx.x;
    if (i < NN) d_deg[i] = 0;
    if (i < NG) d_gcnt[i] = 0;
    if (i < NG * DD) d_gsum[i] = 0.f;
    if (i >= NN * DD / 8) return;
    float4 a = in[2 * i], b = in[2 * i + 1];
    __half2 p0 = __floats2half2_rn(a.x, a.y);
    __half2 p1 = __floats2half2_rn(a.z, a.w);
    __half2 p2 = __floats2half2_rn(b.x, b.y);
    __half2 p3 = __floats2half2_rn(b.z, b.w);
    uint4 o;
    o.x = *(uint32_t*)&p0; o.y = *(uint32_t*)&p1;
    o.z = *(uint32_t*)&p2; o.w = *(uint32_t*)&p3;
    out[i] = o;
}

// both layers' weights -> combined [N=128][K=256] fp16 images
__global__ void k_cvtw(const float* __restrict__ W1s, const float* __restrict__ W1n,
                       const float* __restrict__ W2s, const float* __restrict__ W2n) {
    int i = blockIdx.x * blockDim.x + threadIdx.x;   // 0..32767
    if (i >= 2 * 128 * 128) return;
    int layer = i >> 14;
    int j = i & 16383;
    int k = j >> 7, n = j & 127;
    const float* Ws = layer ? W2s : W1s;
    const float* Wn = layer ? W2n : W1n;
    d_wimg[layer][n * 256 + k]       = __float2half_rn(Ws[k * 128 + n]);
    d_wimg[layer][n * 256 + 128 + k] = __float2half_rn(Wn[k * 128 + n]);
}

// ---------------- CSR build (counting sort by dst) ----------------
__global__ void k_count(const int* __restrict__ dst, const int* __restrict__ gid) {
    int i = blockIdx.x * blockDim.x + threadIdx.x;
    if (i < NE) atomicAdd(&d_deg[dst[i]], 1);
    if (i < NN) atomicAdd(&d_gcnt[gid[i]], 1);
}

__global__ void k_scan1() {
    __shared__ int wsum[16];
    int t = threadIdx.x, lane = t & 31, w = t >> 5;
    int i = blockIdx.x * SBS + t;
    int v = (i < NN) ? d_deg[i] : 0;
    int x = v;
#pragma unroll
    for (int s = 1; s < 32; s <<= 1) {
        int y = __shfl_up_sync(0xFFFFFFFFu, x, s);
        if (lane >= s) x += y;
    }
    if (lane == 31) wsum[w] = x;
    __syncthreads();
    if (w == 0) {
        int ws = (lane < 16) ? wsum[lane] : 0;
#pragma unroll
        for (int s = 1; s < 16; s <<= 1) {
            int y = __shfl_up_sync(0xFFFFFFFFu, ws, s);
            if (lane >= s) ws += y;
        }
        if (lane < 16) wsum[lane] = ws;
    }
    __syncthreads();
    int incl = x + ((w > 0) ? wsum[w - 1] : 0);
    if (i < NN) d_off[i] = incl - v;
    if (t == SBS - 1) d_bsum[blockIdx.x] = incl;
}

__global__ void k_scan2() {
    __shared__ int wsum[8];
    int t = threadIdx.x, lane = t & 31, w = t >> 5;
    int v = (t < SNB) ? d_bsum[t] : 0;
    int x = v;
#pragma unroll
    for (int s = 1; s < 32; s <<= 1) {
        int y = __shfl_up_sync(0xFFFFFFFFu, x, s);
        if (lane >= s) x += y;
    }
    if (lane == 31) wsum[w] = x;
    __syncthreads();
    if (w == 0) {
        int ws = (lane < 8) ? wsum[lane] : 0;
#pragma unroll
        for (int s = 1; s < 8; s <<= 1) {
            int y = __shfl_up_sync(0xFFFFFFFFu, ws, s);
            if (lane >= s) ws += y;
        }
        if (lane < 8) wsum[lane] = ws;
    }
    __syncthreads();
    int incl = x + ((w > 0) ? wsum[w - 1] : 0);
    if (t < SNB) d_bsum[t] = incl - v;
}

__global__ void k_scan3() {
    int i = blockIdx.x * blockDim.x + threadIdx.x;
    if (i < NN) {
        int v = d_off[i] + d_bsum[i / SBS];
        d_off[i] = v;
        d_cursor[i] = v;
    }
    if (i == 0) d_off[NN] = NE;
}

__global__ void k_scatter(const int* __restrict__ src, const int* __restrict__ dst) {
    int e = blockIdx.x * blockDim.x + threadIdx.x;
    if (e < NE) {
        int p = atomicAdd(&d_cursor[dst[e]], 1);
        d_sorted[p] = src[e];
    }
}

// ---------------- aggregation (fp16 gather, fp32 accumulate) ----------------
__global__ void k_agg(const uint2* __restrict__ feat) {
    int warp = (blockIdx.x * blockDim.x + threadIdx.x) >> 5;
    int lane = threadIdx.x & 31;
    if (warp >= NN) return;
    int e0 = d_off[warp];
    int e1 = d_off[warp + 1];
    float ax = 0.f, ay = 0.f, az = 0.f, aw = 0.f;
#pragma unroll 8
    for (int e = e0; e < e1; e++) {
        int s = __ldg(&d_sorted[e]);
        uint2 v = __ldg(&feat[s * 32 + lane]);
        float2 p0 = __half22float2(*(__half2*)&v.x);
        float2 p1 = __half22float2(*(__half2*)&v.y);
        ax += p0.x; ay += p0.y;
        az += p1.x; aw += p1.y;
    }
    float inv = 1.0f / fmaxf((float)(e1 - e0), 1.0f);
    __half2 q0 = __floats2half2_rn(ax * inv, ay * inv);
    __half2 q1 = __floats2half2_rn(az * inv, aw * inv);
    uint2 o; o.x = *(uint32_t*)&q0; o.y = *(uint32_t*)&q1;
    ((uint2*)d_neighb)[warp * 32 + lane] = o;
}

// ---------------- fused dual GEMM via mma.sync (HMMA fp16) ----------------
// D[128m,128n] = [As|An](128x256) @ Bimg(128n x 256k)^T, K=256, one shot.
#define ROWB 528                         // padded row stride in bytes (264 halves)
#define SMA  (128 * ROWB)                // 67584
#define SM_TOT (2 * SMA)                 // 135168

__global__ void __launch_bounds__(256, 1) k_gemm_mma(
    const uint4* __restrict__ Aself, const uint4* __restrict__ Aneigh,
    const uint4* __restrict__ Bimg, const float* __restrict__ bias,
    uint32_t* __restrict__ outp, int relu)
{
    extern __shared__ __align__(16) char smem[];
    char* sA = smem;
    char* sB = smem + SMA;
    const int tid = threadIdx.x;
    const int wid = tid >> 5;
    const int lane = tid & 31;
    const int m_base = blockIdx.x * 128;

    // stage A: rows = nodes, cols 0-127 self / 128-255 neigh (fp16)
#pragma unroll
    for (int it = 0; it < 16; it++) {
        int idx = it * 256 + tid;           // 0..4095
        int row = idx >> 5, q = idx & 31;   // q: uint4 within 256-half row
        int m = m_base + row;
        uint4 v = make_uint4(0, 0, 0, 0);
        if (m < NN) v = (q < 16) ? Aself[m * 16 + q] : Aneigh[m * 16 + (q - 16)];
        *(uint4*)(sA + row * ROWB + q * 16) = v;
    }
    // stage B: [n][k] fp16, flat from global
#pragma unroll
    for (int it = 0; it < 16; it++) {
        int idx = it * 256 + tid;
        int row = idx >> 5, q = idx & 31;
        *(uint4*)(sB + row * ROWB + q * 16) = Bimg[idx];
    }
    __syncthreads();

    const int warpM = wid >> 1;   // 0..3 -> 32-row band
    const int warpN = wid & 1;    // 0..1 -> 64-col band

    float acc[2][8][4];
#pragma unroll
    for (int i = 0; i < 2; i++)
#pragma unroll
        for (int j = 0; j < 8; j++)
#pragma unroll
            for (int p = 0; p < 4; p++) acc[i][j][p] = 0.f;

    uint32_t aBase = smem_to_u32(sA) + (warpM * 32 + (lane & 15)) * ROWB + (lane >> 4) * 16;
    uint32_t bBase = smem_to_u32(sB) +
                     (warpN * 64 + (lane & 7) + ((lane >> 4) & 1) * 8) * ROWB +
                     ((lane >> 3) & 1) * 16;

#pragma unroll
    for (int ks = 0; ks < 16; ks++) {
        uint32_t a[2][4];
        ldsm4(a[0], aBase + ks * 32);
        ldsm4(a[1], aBase + 16 * ROWB + ks * 32);
        uint32_t b[4][4];
#pragma unroll
        for (int nb = 0; nb < 4; nb++)
            ldsm4(b[nb], bBase + nb * 16 * ROWB + ks * 32);
#pragma unroll
        for (int mi = 0; mi < 2; mi++)
#pragma unroll
            for (int nb = 0; nb < 4; nb++) {
                mma_f16(acc[mi][2 * nb],     a[mi], &b[nb][0]);
                mma_f16(acc[mi][2 * nb + 1], a[mi], &b[nb][2]);
            }
    }

    // epilogue: bias + optional relu, fp16 pairs to global
    const int qcol = 2 * (lane & 3);
    const int qrow = lane >> 2;
#pragma unroll
    for (int ni = 0; ni < 8; ni++) {
        int n = warpN * 64 + ni * 8 + qcol;
        float b0 = bias[n], b1 = bias[n + 1];
#pragma unroll
        for (int mi = 0; mi < 2; mi++) {
            int m0 = m_base + warpM * 32 + mi * 16 + qrow;
#pragma unroll
            for (int half = 0; half < 2; half++) {
                int m = m0 + half * 8;
                if (m >= NN) continue;
                float f0 = acc[mi][ni][2 * half]     + b0;
                float f1 = acc[mi][ni][2 * half + 1] + b1;
                if (relu) { f0 = fmaxf(f0, 0.f); f1 = fmaxf(f1, 0.f); }
                __half2 pk = __floats2half2_rn(f0, f1);
                outp[m * 64 + n / 2] = *(uint32_t*)&pk;
            }
        }
    }
}

// ---------------- parallel graph pooling (atomic partial sums) ----------------
#define PB 64   // nodes per block
__global__ void k_pool(const __half* __restrict__ x2, const int* __restrict__ gid) {
    int b = blockIdx.x;
    int t = threadIdx.x;
    int col = t & 127;
    int half = t >> 7;
    int n0 = b * PB + half * (PB / 2);
    int n1 = n0 + PB / 2;
    if (n1 > NN) n1 = NN;
    if (n0 >= n1) return;
    float acc = 0.f;
    int cur = gid[n0];
    for (int r = n0; r < n1; r++) {
        int g = __ldg(&gid[r]);
        if (g != cur) {
            atomicAdd(&d_gsum[cur * DD + col], acc);
            acc = 0.f;
            cur = g;
        }
        acc += __half2float(x2[(size_t)r * DD + col]);
    }
    atomicAdd(&d_gsum[cur * DD + col], acc);
}

// ---------------- classifier: out[g] = (gsum[g]/cnt) @ Wc + bc ----------------
__global__ void k_cls(const float* __restrict__ Wc, const float* __restrict__ bc,
                      float* __restrict__ out) {
    __shared__ float sm[DD];
    int g = blockIdx.x;
    int t = threadIdx.x;   // 128 threads
    float cnt = fmaxf((float)d_gcnt[g], 1.0f);
    sm[t] = d_gsum[g * DD + t] / cnt;
    __syncthreads();
    if (t < NCLS) {
        float o = bc[t];
#pragma unroll 4
        for (int k = 0; k < DD; k++) o += sm[k] * Wc[k * NCLS + t];
        out[g * NCLS + t] = o;
    }
}

// ---------------- launch ----------------
extern "C" void kernel_launch(void* const* d_in, const int* in_sizes, int n_in,
                              void* d_out, int out_size)
{
    const float* h   = (const float*)d_in[0];
    const int*   src = (const int*)d_in[1];
    const int*   dst = (const int*)d_in[2];
    const int*   gid = (const int*)d_in[3];
    int wb = (in_sizes[4] == 1) ? 5 : 4;
    const float* W1s = (const float*)d_in[wb + 0];
    const float* W1n = (const float*)d_in[wb + 1];
    const float* b1  = (const float*)d_in[wb + 2];
    const float* W2s = (const float*)d_in[wb + 3];
    const float* W2n = (const float*)d_in[wb + 4];
    const float* b2  = (const float*)d_in[wb + 5];
    const float* Wc  = (const float*)d_in[wb + 6];
    const float* bc  = (const float*)d_in[wb + 7];
    float* out = (float*)d_out;

    void *phb, *pnb, *px1, *px2, *pw;
    cudaGetSymbolAddress(&phb, d_hb);
    cudaGetSymbolAddress(&pnb, d_neighb);
    cudaGetSymbolAddress(&px1, d_x1b);
    cudaGetSymbolAddress(&px2, d_x2b);
    cudaGetSymbolAddress(&pw, d_wimg);
    __half* hb = (__half*)phb;
    __half* nb = (__half*)pnb;
    __half* x1 = (__half*)px1;
    __half* x2 = (__half*)px2;
    const uint4* wimg = (const uint4*)pw;

    static int smem_set = 0;
    if (!smem_set) {
        cudaFuncSetAttribute(k_gemm_mma, cudaFuncAttributeMaxDynamicSharedMemorySize, SM_TOT);
        smem_set = 1;
    }

    // conversions (cvth also zeroes deg/gcnt/gsum)
    k_cvth<<<(NN * DD / 8 + 255) / 256, 256>>>((const float4*)h, (uint4*)hb);
    k_cvtw<<<128, 256>>>(W1s, W1n, W2s, W2n);

    // CSR by dst (counting sort)
    k_count<<<(NE + 255) / 256, 256>>>(dst, gid);
    k_scan1<<<SNB, SBS>>>();
    k_scan2<<<1, 256>>>();
    k_scan3<<<(NN + 255) / 256, 256>>>();
    k_scatter<<<(NE + 255) / 256, 256>>>(src, dst);

    const int GB = (NN + 127) / 128;   // 782 tiles
    const uint4* B1 = wimg;            // each image = 4096 uint4
    const uint4* B2 = wimg + 4096;

    // layer 1
    k_agg<<<NN / 8, 256>>>((const uint2*)hb);
    k_gemm_mma<<<GB, 256, SM_TOT>>>((const uint4*)hb, (const uint4*)nb, B1, b1,
                                    (uint32_t*)x1, 1);
    // layer 2
    k_agg<<<NN / 8, 256>>>((const uint2*)x1);
    k_gemm_mma<<<GB, 256, SM_TOT>>>((const uint4*)x1, (const uint4*)nb, B2, b2,
                                    (uint32_t*)x2, 0);

    // pooling + classifier
    k_pool<<<(NN + PB - 1) / PB, 256>>>(x2, gid);
    k_cls<<<NG, 128>>>(Wc, bc, out);
}

// round 7
// speedup vs baseline: 1.9025x; 1.0219x over previous
#include <cuda_runtime.h>
#include <cuda_fp16.h>
#include <cstdint>

#define NN   100000
#define NE   1600000
#define DD   128
#define NG   64
#define NCLS 16
#define SBS  512
#define SNB  ((NN + SBS - 1) / SBS)   // 196

// ---------------- device scratch (no allocs allowed) ----------------
__device__ __align__(16) __half d_hb[NN * DD];      // h in fp16
__device__ __align__(16) __half d_neighb[NN * DD];  // aggregated (fp16)
__device__ __align__(16) __half d_x1b[NN * DD];
__device__ __align__(16) __half d_x2b[NN * DD];
__device__ __align__(16) __half d_wimg[2][128 * 256]; // [layer][n][k0..255]
__device__ float d_gsum[NG * DD];
__device__ int d_deg[NN];
__device__ int d_off[NN + 1];
__device__ int d_cursor[NN];
__device__ int d_sorted[NE];
__device__ int d_gcnt[NG];
__device__ int d_bsum[SNB];

// ---------------- PTX helpers ----------------
__device__ __forceinline__ uint32_t smem_to_u32(const void* p) {
    uint32_t a;
    asm("{ .reg .u64 t; cvta.to.shared.u64 t, %1; cvt.u32.u64 %0, t; }" : "=r"(a) : "l"(p));
    return a;
}
__device__ __forceinline__ void ldsm4(uint32_t* r, uint32_t addr) {
    asm volatile("ldmatrix.sync.aligned.m8n8.x4.shared.b16 {%0,%1,%2,%3}, [%4];"
                 : "=r"(r[0]), "=r"(r[1]), "=r"(r[2]), "=r"(r[3]) : "r"(addr));
}
__device__ __forceinline__ void mma_f16(float* c, const uint32_t* a, const uint32_t* b) {
    asm volatile(
        "mma.sync.aligned.m16n8k16.row.col.f32.f16.f16.f32 "
        "{%0,%1,%2,%3},{%4,%5,%6,%7},{%8,%9},{%0,%1,%2,%3};"
        : "+f"(c[0]), "+f"(c[1]), "+f"(c[2]), "+f"(c[3])
        : "r"(a[0]), "r"(a[1]), "r"(a[2]), "r"(a[3]), "r"(b[0]), "r"(b[1]));
}

// ---------------- weights conversion + counter zeroing (launch #1) ----------------
__global__ void k_cvtw(const float* __restrict__ W1s, const float* __restrict__ W1n,
                       const float* __restrict__ W2s, const float* __restrict__ W2n) {
    int i = blockIdx.x * blockDim.x + threadIdx.x;   // grid covers 100096 threads
    if (i < NN) d_deg[i] = 0;
    if (i < NG) d_gcnt[i] = 0;
    if (i < NG * DD) d_gsum[i] = 0.f;
    if (i >= 2 * 128 * 128) return;
    int layer = i >> 14;
    int j = i & 16383;
    int k = j >> 7, n = j & 127;
    const float* Ws = layer ? W2s : W1s;
    const float* Wn = layer ? W2n : W1n;
    d_wimg[layer][n * 256 + k]       = __float2half_rn(Ws[k * 128 + n]);
    d_wimg[layer][n * 256 + 128 + k] = __float2half_rn(Wn[k * 128 + n]);
}

// ---------------- fused: h fp32->fp16 + degree/graph counting (launch #2) ----------------
__global__ void k_cvth_count(const float4* __restrict__ in, uint4* __restrict__ out,
                             const int* __restrict__ dst, const int* __restrict__ gid) {
    int i = blockIdx.x * blockDim.x + threadIdx.x;   // 1.6M both
    if (i < NE) atomicAdd(&d_deg[dst[i]], 1);
    if (i < NN) atomicAdd(&d_gcnt[gid[i]], 1);
    if (i >= NN * DD / 8) return;
    float4 a = in[2 * i], b = in[2 * i + 1];
    __half2 p0 = __floats2half2_rn(a.x, a.y);
    __half2 p1 = __floats2half2_rn(a.z, a.w);
    __half2 p2 = __floats2half2_rn(b.x, b.y);
    __half2 p3 = __floats2half2_rn(b.z, b.w);
    uint4 o;
    o.x = *(uint32_t*)&p0; o.y = *(uint32_t*)&p1;
    o.z = *(uint32_t*)&p2; o.w = *(uint32_t*)&p3;
    out[i] = o;
}

// ---------------- scan over degrees (launch #3) ----------------
__global__ void k_scan1() {
    __shared__ int wsum[16];
    int t = threadIdx.x, lane = t & 31, w = t >> 5;
    int i = blockIdx.x * SBS + t;
    int v = (i < NN) ? d_deg[i] : 0;
    int x = v;
#pragma unroll
    for (int s = 1; s < 32; s <<= 1) {
        int y = __shfl_up_sync(0xFFFFFFFFu, x, s);
        if (lane >= s) x += y;
    }
    if (lane == 31) wsum[w] = x;
    __syncthreads();
    if (w == 0) {
        int ws = (lane < 16) ? wsum[lane] : 0;
#pragma unroll
        for (int s = 1; s < 16; s <<= 1) {
            int y = __shfl_up_sync(0xFFFFFFFFu, ws, s);
            if (lane >= s) ws += y;
        }
        if (lane < 16) wsum[lane] = ws;
    }
    __syncthreads();
    int incl = x + ((w > 0) ? wsum[w - 1] : 0);
    if (i < NN) d_off[i] = incl - v;          // local exclusive
    if (t == SBS - 1) d_bsum[blockIdx.x] = incl;  // block total
}

// ---------------- block-prefix + apply (launch #4, merges old scan2+scan3) ----------------
__global__ void k_scanB() {
    __shared__ int spre;
    int t = threadIdx.x, b = blockIdx.x;
    // warp 0 computes prefix = sum(d_bsum[0..b))
    if (t < 32) {
        int acc = 0;
        for (int j = t; j < b; j += 32) acc += d_bsum[j];
#pragma unroll
        for (int s = 16; s > 0; s >>= 1)
            acc += __shfl_down_sync(0xFFFFFFFFu, acc, s);
        if (t == 0) spre = acc;
    }
    __syncthreads();
    int pre = spre;
    int i = b * SBS + t;
    if (i < NN) {
        int v = d_off[i] + pre;
        d_off[i] = v;
        d_cursor[i] = v;
    }
    if (i == NN) d_off[NN] = NE;
}

// ---------------- scatter edges by dst (launch #5) ----------------
__global__ void k_scatter(const int* __restrict__ src, const int* __restrict__ dst) {
    int e = blockIdx.x * blockDim.x + threadIdx.x;
    if (e < NE) {
        int p = atomicAdd(&d_cursor[dst[e]], 1);
        d_sorted[p] = src[e];
    }
}

// ---------------- aggregation (launch #6 -> ncu capture target) ----------------
__global__ void k_agg(const uint2* __restrict__ feat) {
    int warp = (blockIdx.x * blockDim.x + threadIdx.x) >> 5;
    int lane = threadIdx.x & 31;
    if (warp >= NN) return;
    int e0 = d_off[warp];
    int e1 = d_off[warp + 1];
    float ax = 0.f, ay = 0.f, az = 0.f, aw = 0.f;
#pragma unroll 8
    for (int e = e0; e < e1; e++) {
        int s = __ldg(&d_sorted[e]);
        uint2 v = __ldg(&feat[s * 32 + lane]);
        float2 p0 = __half22float2(*(__half2*)&v.x);
        float2 p1 = __half22float2(*(__half2*)&v.y);
        ax += p0.x; ay += p0.y;
        az += p1.x; aw += p1.y;
    }
    float inv = 1.0f / fmaxf((float)(e1 - e0), 1.0f);
    __half2 q0 = __floats2half2_rn(ax * inv, ay * inv);
    __half2 q1 = __floats2half2_rn(az * inv, aw * inv);
    uint2 o; o.x = *(uint32_t*)&q0; o.y = *(uint32_t*)&q1;
    ((uint2*)d_neighb)[warp * 32 + lane] = o;
}

// ---------------- fused dual GEMM via mma.sync (HMMA fp16) ----------------
// D[128m,128n] = [As|An](128x256) @ Bimg(128n x 256k)^T, K=256, one shot.
#define ROWB 528                         // padded row stride in bytes (264 halves)
#define SMA  (128 * ROWB)                // 67584
#define SM_TOT (2 * SMA)                 // 135168

__global__ void __launch_bounds__(256, 1) k_gemm_mma(
    const uint4* __restrict__ Aself, const uint4* __restrict__ Aneigh,
    const uint4* __restrict__ Bimg, const float* __restrict__ bias,
    uint32_t* __restrict__ outp, int relu)
{
    extern __shared__ __align__(16) char smem[];
    char* sA = smem;
    char* sB = smem + SMA;
    const int tid = threadIdx.x;
    const int wid = tid >> 5;
    const int lane = tid & 31;
    const int m_base = blockIdx.x * 128;

    // stage A: rows = nodes, cols 0-127 self / 128-255 neigh (fp16)
#pragma unroll
    for (int it = 0; it < 16; it++) {
        int idx = it * 256 + tid;           // 0..4095
        int row = idx >> 5, q = idx & 31;   // q: uint4 within 256-half row
        int m = m_base + row;
        uint4 v = make_uint4(0, 0, 0, 0);
        if (m < NN) v = (q < 16) ? Aself[m * 16 + q] : Aneigh[m * 16 + (q - 16)];
        *(uint4*)(sA + row * ROWB + q * 16) = v;
    }
    // stage B: [n][k] fp16, flat from global
#pragma unroll
    for (int it = 0; it < 16; it++) {
        int idx = it * 256 + tid;
        int row = idx >> 5, q = idx & 31;
        *(uint4*)(sB + row * ROWB + q * 16) = Bimg[idx];
    }
    __syncthreads();

    const int warpM = wid >> 1;   // 0..3 -> 32-row band
    const int warpN = wid & 1;    // 0..1 -> 64-col band

    float acc[2][8][4];
#pragma unroll
    for (int i = 0; i < 2; i++)
#pragma unroll
        for (int j = 0; j < 8; j++)
#pragma unroll
            for (int p = 0; p < 4; p++) acc[i][j][p] = 0.f;

    uint32_t aBase = smem_to_u32(sA) + (warpM * 32 + (lane & 15)) * ROWB + (lane >> 4) * 16;
    uint32_t bBase = smem_to_u32(sB) +
                     (warpN * 64 + (lane & 7) + ((lane >> 4) & 1) * 8) * ROWB +
                     ((lane >> 3) & 1) * 16;

#pragma unroll
    for (int ks = 0; ks < 16; ks++) {
        uint32_t a[2][4];
        ldsm4(a[0], aBase + ks * 32);
        ldsm4(a[1], aBase + 16 * ROWB + ks * 32);
        uint32_t b[4][4];
#pragma unroll
        for (int nb = 0; nb < 4; nb++)
            ldsm4(b[nb], bBase + nb * 16 * ROWB + ks * 32);
#pragma unroll
        for (int mi = 0; mi < 2; mi++)
#pragma unroll
            for (int nb = 0; nb < 4; nb++) {
                mma_f16(acc[mi][2 * nb],     a[mi], &b[nb][0]);
                mma_f16(acc[mi][2 * nb + 1], a[mi], &b[nb][2]);
            }
    }

    // epilogue: bias + optional relu, fp16 pairs to global
    const int qcol = 2 * (lane & 3);
    const int qrow = lane >> 2;
#pragma unroll
    for (int ni = 0; ni < 8; ni++) {
        int n = warpN * 64 + ni * 8 + qcol;
        float b0 = bias[n], b1 = bias[n + 1];
#pragma unroll
        for (int mi = 0; mi < 2; mi++) {
            int m0 = m_base + warpM * 32 + mi * 16 + qrow;
#pragma unroll
            for (int half = 0; half < 2; half++) {
                int m = m0 + half * 8;
                if (m >= NN) continue;
                float f0 = acc[mi][ni][2 * half]     + b0;
                float f1 = acc[mi][ni][2 * half + 1] + b1;
                if (relu) { f0 = fmaxf(f0, 0.f); f1 = fmaxf(f1, 0.f); }
                __half2 pk = __floats2half2_rn(f0, f1);
                outp[m * 64 + n / 2] = *(uint32_t*)&pk;
            }
        }
    }
}

// ---------------- parallel graph pooling (atomic partial sums) ----------------
#define PB 64   // nodes per block
__global__ void k_pool(const __half* __restrict__ x2, const int* __restrict__ gid) {
    int b = blockIdx.x;
    int t = threadIdx.x;
    int col = t & 127;
    int half = t >> 7;
    int n0 = b * PB + half * (PB / 2);
    int n1 = n0 + PB / 2;
    if (n1 > NN) n1 = NN;
    if (n0 >= n1) return;
    float acc = 0.f;
    int cur = gid[n0];
    for (int r = n0; r < n1; r++) {
        int g = __ldg(&gid[r]);
        if (g != cur) {
            atomicAdd(&d_gsum[cur * DD + col], acc);
            acc = 0.f;
            cur = g;
        }
        acc += __half2float(x2[(size_t)r * DD + col]);
    }
    atomicAdd(&d_gsum[cur * DD + col], acc);
}

// ---------------- classifier: out[g] = (gsum[g]/cnt) @ Wc + bc ----------------
__global__ void k_cls(const float* __restrict__ Wc, const float* __restrict__ bc,
                      float* __restrict__ out) {
    __shared__ float sm[DD];
    int g = blockIdx.x;
    int t = threadIdx.x;   // 128 threads
    float cnt = fmaxf((float)d_gcnt[g], 1.0f);
    sm[t] = d_gsum[g * DD + t] / cnt;
    __syncthreads();
    if (t < NCLS) {
        float o = bc[t];
#pragma unroll 4
        for (int k = 0; k < DD; k++) o += sm[k] * Wc[k * NCLS + t];
        out[g * NCLS + t] = o;
    }
}

// ---------------- launch ----------------
extern "C" void kernel_launch(void* const* d_in, const int* in_sizes, int n_in,
                              void* d_out, int out_size)
{
    const float* h   = (const float*)d_in[0];
    const int*   src = (const int*)d_in[1];
    const int*   dst = (const int*)d_in[2];
    const int*   gid = (const int*)d_in[3];
    int wb = (in_sizes[4] == 1) ? 5 : 4;
    const float* W1s = (const float*)d_in[wb + 0];
    const float* W1n = (const float*)d_in[wb + 1];
    const float* b1  = (const float*)d_in[wb + 2];
    const float* W2s = (const float*)d_in[wb + 3];
    const float* W2n = (const float*)d_in[wb + 4];
    const float* b2  = (const float*)d_in[wb + 5];
    const float* Wc  = (const float*)d_in[wb + 6];
    const float* bc  = (const float*)d_in[wb + 7];
    float* out = (float*)d_out;

    void *phb, *pnb, *px1, *px2, *pw;
    cudaGetSymbolAddress(&phb, d_hb);
    cudaGetSymbolAddress(&pnb, d_neighb);
    cudaGetSymbolAddress(&px1, d_x1b);
    cudaGetSymbolAddress(&px2, d_x2b);
    cudaGetSymbolAddress(&pw, d_wimg);
    __half* hb = (__half*)phb;
    __half* nb = (__half*)pnb;
    __half* x1 = (__half*)px1;
    __half* x2 = (__half*)px2;
    const uint4* wimg = (const uint4*)pw;

    static int smem_set = 0;
    if (!smem_set) {
        cudaFuncSetAttribute(k_gemm_mma, cudaFuncAttributeMaxDynamicSharedMemorySize, SM_TOT);
        smem_set = 1;
    }

    // #1: weights + zeroing (covers NN threads for d_deg)
    k_cvtw<<<(NN + 255) / 256, 256>>>(W1s, W1n, W2s, W2n);
    // #2: h conversion fused with degree/graph counting
    k_cvth_count<<<(NN * DD / 8 + 255) / 256, 256>>>((const float4*)h, (uint4*)hb, dst, gid);
    // #3-#5: CSR build
    k_scan1<<<SNB, SBS>>>();
    k_scanB<<<SNB, SBS>>>();
    k_scatter<<<(NE + 255) / 256, 256>>>(src, dst);

    const int GB = (NN + 127) / 128;   // 782 tiles
    const uint4* B1 = wimg;            // each image = 4096 uint4
    const uint4* B2 = wimg + 4096;

    // #6: layer-1 aggregation (ncu -s 5 -c 1 captures this)
    k_agg<<<NN / 8, 256>>>((const uint2*)hb);
    // #7: layer-1 fused GEMM
    k_gemm_mma<<<GB, 256, SM_TOT>>>((const uint4*)hb, (const uint4*)nb, B1, b1,
                                    (uint32_t*)x1, 1);
    // #8-#9: layer 2
    k_agg<<<NN / 8, 256>>>((const uint2*)x1);
    k_gemm_mma<<<GB, 256, SM_TOT>>>((const uint4*)x1, (const uint4*)nb, B2, b2,
                                    (uint32_t*)x2, 0);

    // #10-#11: pooling + classifier
    k_pool<<<(NN + PB - 1) / PB, 256>>>(x2, gid);
    k_cls<<<NG, 128>>>(Wc, bc, out);
}

// round 8
// speedup vs baseline: 2.0648x; 1.0853x over previous
#include <cuda_runtime.h>
#include <cuda_fp16.h>
#include <cstdint>

#define NN   100000
#define NE   1600000
#define DD   128
#define NG   64
#define NCLS 16
#define SBS  512
#define SNB  ((NN + SBS - 1) / SBS)   // 196

// ---------------- device scratch (no allocs; zero-init on load) ----------------
__device__ __align__(16) __half d_hb[NN * DD];      // h in fp16
__device__ __align__(16) __half d_neighb[NN * DD];  // aggregated (fp16)
__device__ __align__(16) __half d_x1b[NN * DD];
__device__ __align__(16) __half d_wimg[2][128 * 256]; // [layer][n][k0..255]
__device__ float d_gsum[NG * DD];
__device__ int d_deg[NN];
__device__ int d_off[NN];
__device__ int d_cursor[NN];
__device__ int d_sorted[NE];
__device__ int d_gcnt[NG];
__device__ int d_total;

// ---------------- PTX helpers ----------------
__device__ __forceinline__ uint32_t smem_to_u32(const void* p) {
    uint32_t a;
    asm("{ .reg .u64 t; cvta.to.shared.u64 t, %1; cvt.u32.u64 %0, t; }" : "=r"(a) : "l"(p));
    return a;
}
__device__ __forceinline__ void ldsm4(uint32_t* r, uint32_t addr) {
    asm volatile("ldmatrix.sync.aligned.m8n8.x4.shared.b16 {%0,%1,%2,%3}, [%4];"
                 : "=r"(r[0]), "=r"(r[1]), "=r"(r[2]), "=r"(r[3]) : "r"(addr));
}
__device__ __forceinline__ void mma_f16(float* c, const uint32_t* a, const uint32_t* b) {
    asm volatile(
        "mma.sync.aligned.m16n8k16.row.col.f32.f16.f16.f32 "
        "{%0,%1,%2,%3},{%4,%5,%6,%7},{%8,%9},{%0,%1,%2,%3};"
        : "+f"(c[0]), "+f"(c[1]), "+f"(c[2]), "+f"(c[3])
        : "r"(a[0]), "r"(a[1]), "r"(a[2]), "r"(a[3]), "r"(b[0]), "r"(b[1]));
}

// ---- #1: h fp32->fp16 + degree/graph counting (counters are 0 at entry) ----
__global__ void k_cvth_count(const float4* __restrict__ in, uint4* __restrict__ out,
                             const int* __restrict__ dst, const int* __restrict__ gid) {
    int i = blockIdx.x * blockDim.x + threadIdx.x;   // covers 1.6M
    if (i < NE) atomicAdd(&d_deg[dst[i]], 1);
    if (i < NN) atomicAdd(&d_gcnt[gid[i]], 1);
    if (i >= NN * DD / 8) return;
    float4 a = in[2 * i], b = in[2 * i + 1];
    __half2 p0 = __floats2half2_rn(a.x, a.y);
    __half2 p1 = __floats2half2_rn(a.z, a.w);
    __half2 p2 = __floats2half2_rn(b.x, b.y);
    __half2 p3 = __floats2half2_rn(b.z, b.w);
    uint4 o;
    o.x = *(uint32_t*)&p0; o.y = *(uint32_t*)&p1;
    o.z = *(uint32_t*)&p2; o.w = *(uint32_t*)&p3;
    out[i] = o;
}

// ---- #2: single-pass scan via atomic ticket (ranges disjoint, order-free) ----
__global__ void k_scan_atomic() {
    __shared__ int wsum[16];
    __shared__ int sbase;
    int t = threadIdx.x, lane = t & 31, w = t >> 5;
    int i = blockIdx.x * SBS + t;
    int v = (i < NN) ? d_deg[i] : 0;
    int x = v;
#pragma unroll
    for (int s = 1; s < 32; s <<= 1) {
        int y = __shfl_up_sync(0xFFFFFFFFu, x, s);
        if (lane >= s) x += y;
    }
    if (lane == 31) wsum[w] = x;
    __syncthreads();
    if (w == 0) {
        int ws = (lane < 16) ? wsum[lane] : 0;
#pragma unroll
        for (int s = 1; s < 16; s <<= 1) {
            int y = __shfl_up_sync(0xFFFFFFFFu, ws, s);
            if (lane >= s) ws += y;
        }
        if (lane < 16) wsum[lane] = ws;
    }
    __syncthreads();
    int incl = x + ((w > 0) ? wsum[w - 1] : 0);
    if (t == SBS - 1) sbase = atomicAdd(&d_total, incl);   // block total = incl of last
    __syncthreads();
    if (i < NN) {
        int off = sbase + incl - v;
        d_off[i] = off;
        d_cursor[i] = off;
    }
}

// ---- #3: scatter edges into per-dst ranges ----
__global__ void k_scatter(const int* __restrict__ src, const int* __restrict__ dst) {
    int e = blockIdx.x * blockDim.x + threadIdx.x;
    if (e < NE) {
        int p = atomicAdd(&d_cursor[dst[e]], 1);
        d_sorted[p] = src[e];
    }
}

// ---- #4 / #7: aggregation (fp16 gather, fp32 accumulate) — PROFILED at #4 ----
__global__ void k_agg(const uint2* __restrict__ feat) {
    int warp = (blockIdx.x * blockDim.x + threadIdx.x) >> 5;
    int lane = threadIdx.x & 31;
    if (warp >= NN) return;
    int e0 = d_off[warp];
    int deg = d_deg[warp];
    int e1 = e0 + deg;
    float ax = 0.f, ay = 0.f, az = 0.f, aw = 0.f;
#pragma unroll 8
    for (int e = e0; e < e1; e++) {
        int s = __ldg(&d_sorted[e]);
        uint2 v = __ldg(&feat[s * 32 + lane]);
        float2 p0 = __half22float2(*(__half2*)&v.x);
        float2 p1 = __half22float2(*(__half2*)&v.y);
        ax += p0.x; ay += p0.y;
        az += p1.x; aw += p1.y;
    }
    float inv = 1.0f / fmaxf((float)deg, 1.0f);
    __half2 q0 = __floats2half2_rn(ax * inv, ay * inv);
    __half2 q1 = __floats2half2_rn(az * inv, aw * inv);
    uint2 o; o.x = *(uint32_t*)&q0; o.y = *(uint32_t*)&q1;
    ((uint2*)d_neighb)[warp * 32 + lane] = o;
}

// ---- #5: weights -> combined [N=128][K=256] fp16 images ----
__global__ void k_cvtw(const float* __restrict__ W1s, const float* __restrict__ W1n,
                       const float* __restrict__ W2s, const float* __restrict__ W2n) {
    int i = blockIdx.x * blockDim.x + threadIdx.x;   // 0..32767
    if (i >= 2 * 128 * 128) return;
    int layer = i >> 14;
    int j = i & 16383;
    int k = j >> 7, n = j & 127;
    const float* Ws = layer ? W2s : W1s;
    const float* Wn = layer ? W2n : W1n;
    d_wimg[layer][n * 256 + k]       = __float2half_rn(Ws[k * 128 + n]);
    d_wimg[layer][n * 256 + 128 + k] = __float2half_rn(Wn[k * 128 + n]);
}

// ---- #6 / #8: fused dual GEMM (HMMA fp16); #8 also pools into d_gsum ----
// D[128m,128n] = [As|An](128x256) @ Bimg(128n x 256k)^T, K=256, one shot.
#define ROWB 528                         // padded row stride in bytes (264 halves)
#define SMA  (128 * ROWB)                // 67584
#define SM_TOT (2 * SMA)                 // 135168

__global__ void __launch_bounds__(256, 1) k_gemm_mma(
    const uint4* __restrict__ Aself, const uint4* __restrict__ Aneigh,
    const uint4* __restrict__ Bimg, const float* __restrict__ bias,
    uint32_t* __restrict__ outp, const int* __restrict__ gid, int mode)
    // mode 0: relu + store fp16; mode 1: no relu, pool into d_gsum (no store)
{
    extern __shared__ __align__(16) char smem[];
    char* sA = smem;
    char* sB = smem + SMA;
    const int tid = threadIdx.x;
    const int wid = tid >> 5;
    const int lane = tid & 31;
    const int m_base = blockIdx.x * 128;

    // stage A: rows = nodes, cols 0-127 self / 128-255 neigh (fp16)
#pragma unroll
    for (int it = 0; it < 16; it++) {
        int idx = it * 256 + tid;           // 0..4095
        int row = idx >> 5, q = idx & 31;   // q: uint4 within 256-half row
        int m = m_base + row;
        uint4 v = make_uint4(0, 0, 0, 0);
        if (m < NN) v = (q < 16) ? Aself[m * 16 + q] : Aneigh[m * 16 + (q - 16)];
        *(uint4*)(sA + row * ROWB + q * 16) = v;
    }
    // stage B: [n][k] fp16, flat from global
#pragma unroll
    for (int it = 0; it < 16; it++) {
        int idx = it * 256 + tid;
        int row = idx >> 5, q = idx & 31;
        *(uint4*)(sB + row * ROWB + q * 16) = Bimg[idx];
    }
    __syncthreads();

    const int warpM = wid >> 1;   // 0..3 -> 32-row band
    const int warpN = wid & 1;    // 0..1 -> 64-col band

    float acc[2][8][4];
#pragma unroll
    for (int i = 0; i < 2; i++)
#pragma unroll
        for (int j = 0; j < 8; j++)
#pragma unroll
            for (int p = 0; p < 4; p++) acc[i][j][p] = 0.f;

    uint32_t aBase = smem_to_u32(sA) + (warpM * 32 + (lane & 15)) * ROWB + (lane >> 4) * 16;
    uint32_t bBase = smem_to_u32(sB) +
                     (warpN * 64 + (lane & 7) + ((lane >> 4) & 1) * 8) * ROWB +
                     ((lane >> 3) & 1) * 16;

#pragma unroll
    for (int ks = 0; ks < 16; ks++) {
        uint32_t a[2][4];
        ldsm4(a[0], aBase + ks * 32);
        ldsm4(a[1], aBase + 16 * ROWB + ks * 32);
        uint32_t b[4][4];
#pragma unroll
        for (int nb = 0; nb < 4; nb++)
            ldsm4(b[nb], bBase + nb * 16 * ROWB + ks * 32);
#pragma unroll
        for (int mi = 0; mi < 2; mi++)
#pragma unroll
            for (int nb = 0; nb < 4; nb++) {
                mma_f16(acc[mi][2 * nb],     a[mi], &b[nb][0]);
                mma_f16(acc[mi][2 * nb + 1], a[mi], &b[nb][2]);
            }
    }

    const int qcol = 2 * (lane & 3);
    const int qrow = lane >> 2;

    if (mode == 0) {
        // epilogue: bias + relu, fp16 pairs to global
#pragma unroll
        for (int ni = 0; ni < 8; ni++) {
            int n = warpN * 64 + ni * 8 + qcol;
            float b0 = bias[n], b1 = bias[n + 1];
#pragma unroll
            for (int mi = 0; mi < 2; mi++) {
                int m0 = m_base + warpM * 32 + mi * 16 + qrow;
#pragma unroll
                for (int half = 0; half < 2; half++) {
                    int m = m0 + half * 8;
                    if (m >= NN) continue;
                    float f0 = fmaxf(acc[mi][ni][2 * half]     + b0, 0.f);
                    float f1 = fmaxf(acc[mi][ni][2 * half + 1] + b1, 0.f);
                    __half2 pk = __floats2half2_rn(f0, f1);
                    outp[m * 64 + n / 2] = *(uint32_t*)&pk;
                }
            }
        }
    } else {
        // epilogue: bias (no relu), per-graph segmented pooling into d_gsum
        __syncthreads();                      // all ldsm reads of sA done
        float* scr = (float*)sA;              // 128x128 fp32 = 65536 B (fits in sA)
        int* sg = (int*)(smem + 65536);       // 512 B for gids (inside sA region)
        if (tid < 128) {
            int m = m_base + tid;
            sg[tid] = (m < NN) ? gid[m] : -1;
        }
#pragma unroll
        for (int ni = 0; ni < 8; ni++) {
            int n = warpN * 64 + ni * 8 + qcol;
            float b0 = bias[n], b1 = bias[n + 1];
#pragma unroll
            for (int mi = 0; mi < 2; mi++) {
                int ml0 = warpM * 32 + mi * 16 + qrow;
#pragma unroll
                for (int half = 0; half < 2; half++) {
                    int ml = ml0 + half * 8;
                    scr[ml * 128 + n]     = acc[mi][ni][2 * half]     + b0;
                    scr[ml * 128 + n + 1] = acc[mi][ni][2 * half + 1] + b1;
                }
            }
        }
        __syncthreads();
        if (tid < 128) {
            float pacc = 0.f;
            int cur = sg[0];
            for (int r = 0; r < 128; r++) {
                int m = m_base + r;
                if (m >= NN) break;
                int g = sg[r];
                if (g != cur) {
                    atomicAdd(&d_gsum[cur * DD + tid], pacc);
                    pacc = 0.f;
                    cur = g;
                }
                pacc += scr[r * 128 + tid];
            }
            atomicAdd(&d_gsum[cur * DD + tid], pacc);
        }
    }
}

// ---- #9: classifier out[g] = (gsum[g]/cnt) @ Wc + bc ----
__global__ void k_cls(const float* __restrict__ Wc, const float* __restrict__ bc,
                      float* __restrict__ out) {
    __shared__ float sm[DD];
    int g = blockIdx.x;
    int t = threadIdx.x;   // 128 threads
    float cnt = fmaxf((float)d_gcnt[g], 1.0f);
    sm[t] = d_gsum[g * DD + t] / cnt;
    __syncthreads();
    if (t < NCLS) {
        float o = bc[t];
#pragma unroll 4
        for (int k = 0; k < DD; k++) o += sm[k] * Wc[k * NCLS + t];
        out[g * NCLS + t] = o;
    }
}

// ---- #10: restore counter invariant (zero at exit == zero at entry) ----
__global__ void k_cleanup() {
    int i = blockIdx.x * blockDim.x + threadIdx.x;
    if (i < NN) d_deg[i] = 0;
    if (i < NG) d_gcnt[i] = 0;
    if (i < NG * DD) d_gsum[i] = 0.f;
    if (i == 0) d_total = 0;
}

// ---------------- launch ----------------
extern "C" void kernel_launch(void* const* d_in, const int* in_sizes, int n_in,
                              void* d_out, int out_size)
{
    const float* h   = (const float*)d_in[0];
    const int*   src = (const int*)d_in[1];
    const int*   dst = (const int*)d_in[2];
    const int*   gid = (const int*)d_in[3];
    int wb = (in_sizes[4] == 1) ? 5 : 4;
    const float* W1s = (const float*)d_in[wb + 0];
    const float* W1n = (const float*)d_in[wb + 1];
    const float* b1  = (const float*)d_in[wb + 2];
    const float* W2s = (const float*)d_in[wb + 3];
    const float* W2n = (const float*)d_in[wb + 4];
    const float* b2  = (const float*)d_in[wb + 5];
    const float* Wc  = (const float*)d_in[wb + 6];
    const float* bc  = (const float*)d_in[wb + 7];
    float* out = (float*)d_out;

    void *phb, *pnb, *px1, *pw;
    cudaGetSymbolAddress(&phb, d_hb);
    cudaGetSymbolAddress(&pnb, d_neighb);
    cudaGetSymbolAddress(&px1, d_x1b);
    cudaGetSymbolAddress(&pw, d_wimg);
    __half* hb = (__half*)phb;
    __half* nb = (__half*)pnb;
    __half* x1 = (__half*)px1;
    const uint4* wimg = (const uint4*)pw;

    cudaFuncSetAttribute(k_gemm_mma, cudaFuncAttributeMaxDynamicSharedMemorySize, SM_TOT);

    const int GB = (NN + 127) / 128;   // 782 tiles
    const uint4* B1 = wimg;            // each image = 4096 uint4
    const uint4* B2 = wimg + 4096;

    // #1: h conversion + degree/graph counting (counters zero at entry)
    k_cvth_count<<<(NN * DD / 8 + 255) / 256, 256>>>((const float4*)h, (uint4*)hb, dst, gid);
    // #2: one-shot scan (atomic ticket)
    k_scan_atomic<<<SNB, SBS>>>();
    // #3: scatter
    k_scatter<<<(NE + 255) / 256, 256>>>(src, dst);
    // #4: layer-1 aggregation  <-- ncu capture slot
    k_agg<<<NN / 8, 256>>>((const uint2*)hb);
    // #5: weight images
    k_cvtw<<<128, 256>>>(W1s, W1n, W2s, W2n);
    // #6: layer-1 GEMM (relu, store x1)
    k_gemm_mma<<<GB, 256, SM_TOT>>>((const uint4*)hb, (const uint4*)nb, B1, b1,
                                    (uint32_t*)x1, gid, 0);
    // #7: layer-2 aggregation
    k_agg<<<NN / 8, 256>>>((const uint2*)x1);
    // #8: layer-2 GEMM + fused graph pooling into d_gsum
    k_gemm_mma<<<GB, 256, SM_TOT>>>((const uint4*)x1, (const uint4*)nb, B2, b2,
                                    (uint32_t*)x1, gid, 1);
    // #9: classifier
    k_cls<<<NG, 128>>>(Wc, bc, out);
    // #10: restore zero invariant for next call
    k_cleanup<<<(NN + 255) / 256, 256>>>();
}

// round 9
// speedup vs baseline: 2.1875x; 1.0594x over previous
#include <cuda_runtime.h>
#include <cuda_fp16.h>
#include <cstdint>

#define NN   100000
#define NE   1600000
#define DD   128
#define NG   64
#define NCLS 16
#define SBS  512
#define SNB  ((NN + SBS - 1) / SBS)   // 196

// ---------------- device scratch (no allocs; zero-init on load) ----------------
__device__ __align__(16) __half d_hb[NN * DD];      // h in fp16
__device__ __align__(16) __half d_neighb[NN * DD];  // aggregated (fp16)
__device__ __align__(16) __half d_x1b[NN * DD];
__device__ __align__(16) __half d_wimg[2][128 * 256]; // [layer][n][k0..255]
__device__ float d_gsum[NG * DD];
__device__ int d_deg[NN];
__device__ int d_off[NN];
__device__ int d_cursor[NN];
__device__ int d_sorted[NE];
__device__ int d_gcnt[NG];
__device__ int d_total;

// ---------------- PTX helpers ----------------
__device__ __forceinline__ uint32_t smem_to_u32(const void* p) {
    uint32_t a;
    asm("{ .reg .u64 t; cvta.to.shared.u64 t, %1; cvt.u32.u64 %0, t; }" : "=r"(a) : "l"(p));
    return a;
}
__device__ __forceinline__ void ldsm4(uint32_t* r, uint32_t addr) {
    asm volatile("ldmatrix.sync.aligned.m8n8.x4.shared.b16 {%0,%1,%2,%3}, [%4];"
                 : "=r"(r[0]), "=r"(r[1]), "=r"(r[2]), "=r"(r[3]) : "r"(addr));
}
__device__ __forceinline__ void mma_f16(float* c, const uint32_t* a, const uint32_t* b) {
    asm volatile(
        "mma.sync.aligned.m16n8k16.row.col.f32.f16.f16.f32 "
        "{%0,%1,%2,%3},{%4,%5,%6,%7},{%8,%9},{%0,%1,%2,%3};"
        : "+f"(c[0]), "+f"(c[1]), "+f"(c[2]), "+f"(c[3])
        : "r"(a[0]), "r"(a[1]), "r"(a[2]), "r"(a[3]), "r"(b[0]), "r"(b[1]));
}

// ---- #1: h fp32->fp16 + degree/graph counting (counters are 0 at entry) ----
__global__ void k_cvth_count(const float4* __restrict__ in, uint4* __restrict__ out,
                             const int* __restrict__ dst, const int* __restrict__ gid) {
    int i = blockIdx.x * blockDim.x + threadIdx.x;   // covers 1.6M
    if (i < NE) atomicAdd(&d_deg[dst[i]], 1);
    if (i < NN) atomicAdd(&d_gcnt[gid[i]], 1);
    if (i >= NN * DD / 8) return;
    float4 a = in[2 * i], b = in[2 * i + 1];
    __half2 p0 = __floats2half2_rn(a.x, a.y);
    __half2 p1 = __floats2half2_rn(a.z, a.w);
    __half2 p2 = __floats2half2_rn(b.x, b.y);
    __half2 p3 = __floats2half2_rn(b.z, b.w);
    uint4 o;
    o.x = *(uint32_t*)&p0; o.y = *(uint32_t*)&p1;
    o.z = *(uint32_t*)&p2; o.w = *(uint32_t*)&p3;
    out[i] = o;
}

// ---- #2: single-pass scan via atomic ticket (ranges disjoint, order-free) ----
__global__ void k_scan_atomic() {
    __shared__ int wsum[16];
    __shared__ int sbase;
    int t = threadIdx.x, lane = t & 31, w = t >> 5;
    int i = blockIdx.x * SBS + t;
    int v = (i < NN) ? d_deg[i] : 0;
    int x = v;
#pragma unroll
    for (int s = 1; s < 32; s <<= 1) {
        int y = __shfl_up_sync(0xFFFFFFFFu, x, s);
        if (lane >= s) x += y;
    }
    if (lane == 31) wsum[w] = x;
    __syncthreads();
    if (w == 0) {
        int ws = (lane < 16) ? wsum[lane] : 0;
#pragma unroll
        for (int s = 1; s < 16; s <<= 1) {
            int y = __shfl_up_sync(0xFFFFFFFFu, ws, s);
            if (lane >= s) ws += y;
        }
        if (lane < 16) wsum[lane] = ws;
    }
    __syncthreads();
    int incl = x + ((w > 0) ? wsum[w - 1] : 0);
    if (t == SBS - 1) sbase = atomicAdd(&d_total, incl);   // block total = incl of last
    __syncthreads();
    if (i < NN) {
        int off = sbase + incl - v;
        d_off[i] = off;
        d_cursor[i] = off;
    }
}

// ---- #3: scatter edges into per-dst ranges ----
__global__ void k_scatter(const int* __restrict__ src, const int* __restrict__ dst) {
    int e = blockIdx.x * blockDim.x + threadIdx.x;
    if (e < NE) {
        int p = atomicAdd(&d_cursor[dst[e]], 1);
        d_sorted[p] = src[e];
    }
}

// ---- #4 / #7: aggregation v2 — 2 edges/iter, uint4 lanes, fp16 accumulate ----
__global__ void k_agg(const uint4* __restrict__ feat) {
    int warp = (blockIdx.x * blockDim.x + threadIdx.x) >> 5;
    int lane = threadIdx.x & 31;
    if (warp >= NN) return;
    const int half = lane >> 4;      // which edge of the pair
    const int sub = lane & 15;       // uint4 index within 256B row
    int e0 = d_off[warp];
    int deg = d_deg[warp];
    int e1 = e0 + deg;

    __half2 a0 = __float2half2_rn(0.f), a1 = a0, a2 = a0, a3 = a0;
    int e = e0;
#pragma unroll 4
    for (; e + 1 < e1; e += 2) {
        int s = __ldg(&d_sorted[e + half]);
        uint4 v = __ldg(&feat[s * 16 + sub]);
        a0 = __hadd2(a0, *(__half2*)&v.x);
        a1 = __hadd2(a1, *(__half2*)&v.y);
        a2 = __hadd2(a2, *(__half2*)&v.z);
        a3 = __hadd2(a3, *(__half2*)&v.w);
    }
    if (e < e1 && half == 0) {       // odd remainder: lanes 0-15 only
        int s = __ldg(&d_sorted[e]);
        uint4 v = __ldg(&feat[s * 16 + sub]);
        a0 = __hadd2(a0, *(__half2*)&v.x);
        a1 = __hadd2(a1, *(__half2*)&v.y);
        a2 = __hadd2(a2, *(__half2*)&v.z);
        a3 = __hadd2(a3, *(__half2*)&v.w);
    }

    // merge the two halves in fp32, scale by 1/deg, pack, write by lanes 0-15
    float2 f0 = __half22float2(a0), f1 = __half22float2(a1);
    float2 f2 = __half22float2(a2), f3 = __half22float2(a3);
    float fs[8] = { f0.x, f0.y, f1.x, f1.y, f2.x, f2.y, f3.x, f3.y };
    float inv = 1.0f / fmaxf((float)deg, 1.0f);
#pragma unroll
    for (int j = 0; j < 8; j++) {
        fs[j] += __shfl_xor_sync(0xFFFFFFFFu, fs[j], 16);
        fs[j] *= inv;
    }
    if (half == 0) {
        __half2 q0 = __floats2half2_rn(fs[0], fs[1]);
        __half2 q1 = __floats2half2_rn(fs[2], fs[3]);
        __half2 q2 = __floats2half2_rn(fs[4], fs[5]);
        __half2 q3 = __floats2half2_rn(fs[6], fs[7]);
        uint4 o;
        o.x = *(uint32_t*)&q0; o.y = *(uint32_t*)&q1;
        o.z = *(uint32_t*)&q2; o.w = *(uint32_t*)&q3;
        ((uint4*)d_neighb)[warp * 16 + sub] = o;
    }
}

// ---- #5: weights -> combined [N=128][K=256] fp16 images ----
__global__ void k_cvtw(const float* __restrict__ W1s, const float* __restrict__ W1n,
                       const float* __restrict__ W2s, const float* __restrict__ W2n) {
    int i = blockIdx.x * blockDim.x + threadIdx.x;   // 0..32767
    if (i >= 2 * 128 * 128) return;
    int layer = i >> 14;
    int j = i & 16383;
    int k = j >> 7, n = j & 127;
    const float* Ws = layer ? W2s : W1s;
    const float* Wn = layer ? W2n : W1n;
    d_wimg[layer][n * 256 + k]       = __float2half_rn(Ws[k * 128 + n]);
    d_wimg[layer][n * 256 + 128 + k] = __float2half_rn(Wn[k * 128 + n]);
}

// ---- #6 / #8: fused dual GEMM (HMMA fp16); #8 also pools into d_gsum ----
// D[128m,128n] = [As|An](128x256) @ Bimg(128n x 256k)^T, K=256, one shot.
#define ROWB 528                         // padded row stride in bytes (264 halves)
#define SMA  (128 * ROWB)                // 67584
#define SM_TOT (2 * SMA)                 // 135168

__global__ void __launch_bounds__(256, 1) k_gemm_mma(
    const uint4* __restrict__ Aself, const uint4* __restrict__ Aneigh,
    const uint4* __restrict__ Bimg, const float* __restrict__ bias,
    uint32_t* __restrict__ outp, const int* __restrict__ gid, int mode)
    // mode 0: relu + store fp16; mode 1: no relu, pool into d_gsum (no store)
{
    extern __shared__ __align__(16) char smem[];
    char* sA = smem;
    char* sB = smem + SMA;
    const int tid = threadIdx.x;
    const int wid = tid >> 5;
    const int lane = tid & 31;
    const int m_base = blockIdx.x * 128;

    // stage A: rows = nodes, cols 0-127 self / 128-255 neigh (fp16)
#pragma unroll
    for (int it = 0; it < 16; it++) {
        int idx = it * 256 + tid;           // 0..4095
        int row = idx >> 5, q = idx & 31;   // q: uint4 within 256-half row
        int m = m_base + row;
        uint4 v = make_uint4(0, 0, 0, 0);
        if (m < NN) v = (q < 16) ? Aself[m * 16 + q] : Aneigh[m * 16 + (q - 16)];
        *(uint4*)(sA + row * ROWB + q * 16) = v;
    }
    // stage B: [n][k] fp16, flat from global
#pragma unroll
    for (int it = 0; it < 16; it++) {
        int idx = it * 256 + tid;
        int row = idx >> 5, q = idx & 31;
        *(uint4*)(sB + row * ROWB + q * 16) = Bimg[idx];
    }
    __syncthreads();

    const int warpM = wid >> 1;   // 0..3 -> 32-row band
    const int warpN = wid & 1;    // 0..1 -> 64-col band

    float acc[2][8][4];
#pragma unroll
    for (int i = 0; i < 2; i++)
#pragma unroll
        for (int j = 0; j < 8; j++)
#pragma unroll
            for (int p = 0; p < 4; p++) acc[i][j][p] = 0.f;

    uint32_t aBase = smem_to_u32(sA) + (warpM * 32 + (lane & 15)) * ROWB + (lane >> 4) * 16;
    uint32_t bBase = smem_to_u32(sB) +
                     (warpN * 64 + (lane & 7) + ((lane >> 4) & 1) * 8) * ROWB +
                     ((lane >> 3) & 1) * 16;

#pragma unroll
    for (int ks = 0; ks < 16; ks++) {
        uint32_t a[2][4];
        ldsm4(a[0], aBase + ks * 32);
        ldsm4(a[1], aBase + 16 * ROWB + ks * 32);
        uint32_t b[4][4];
#pragma unroll
        for (int nb = 0; nb < 4; nb++)
            ldsm4(b[nb], bBase + nb * 16 * ROWB + ks * 32);
#pragma unroll
        for (int mi = 0; mi < 2; mi++)
#pragma unroll
            for (int nb = 0; nb < 4; nb++) {
                mma_f16(acc[mi][2 * nb],     a[mi], &b[nb][0]);
                mma_f16(acc[mi][2 * nb + 1], a[mi], &b[nb][2]);
            }
    }

    const int qcol = 2 * (lane & 3);
    const int qrow = lane >> 2;

    if (mode == 0) {
        // epilogue: bias + relu, fp16 pairs to global
#pragma unroll
        for (int ni = 0; ni < 8; ni++) {
            int n = warpN * 64 + ni * 8 + qcol;
            float b0 = bias[n], b1 = bias[n + 1];
#pragma unroll
            for (int mi = 0; mi < 2; mi++) {
                int m0 = m_base + warpM * 32 + mi * 16 + qrow;
#pragma unroll
                for (int half = 0; half < 2; half++) {
                    int m = m0 + half * 8;
                    if (m >= NN) continue;
                    float f0 = fmaxf(acc[mi][ni][2 * half]     + b0, 0.f);
                    float f1 = fmaxf(acc[mi][ni][2 * half + 1] + b1, 0.f);
                    __half2 pk = __floats2half2_rn(f0, f1);
                    outp[m * 64 + n / 2] = *(uint32_t*)&pk;
                }
            }
        }
    } else {
        // epilogue: bias (no relu), per-graph segmented pooling into d_gsum
        __syncthreads();                      // all ldsm reads of sA done
        float* scr = (float*)sA;              // 128x128 fp32 = 65536 B (fits in sA)
        int* sg = (int*)(smem + 65536);       // 512 B for gids (inside sA region)
        if (tid < 128) {
            int m = m_base + tid;
            sg[tid] = (m < NN) ? gid[m] : -1;
        }
#pragma unroll
        for (int ni = 0; ni < 8; ni++) {
            int n = warpN * 64 + ni * 8 + qcol;
            float b0 = bias[n], b1 = bias[n + 1];
#pragma unroll
            for (int mi = 0; mi < 2; mi++) {
                int ml0 = warpM * 32 + mi * 16 + qrow;
#pragma unroll
                for (int half = 0; half < 2; half++) {
                    int ml = ml0 + half * 8;
                    scr[ml * 128 + n]     = acc[mi][ni][2 * half]     + b0;
                    scr[ml * 128 + n + 1] = acc[mi][ni][2 * half + 1] + b1;
                }
            }
        }
        __syncthreads();
        if (tid < 128) {
            float pacc = 0.f;
            int cur = sg[0];
            for (int r = 0; r < 128; r++) {
                int m = m_base + r;
                if (m >= NN) break;
                int g = sg[r];
                if (g != cur) {
                    atomicAdd(&d_gsum[cur * DD + tid], pacc);
                    pacc = 0.f;
                    cur = g;
                }
                pacc += scr[r * 128 + tid];
            }
            atomicAdd(&d_gsum[cur * DD + tid], pacc);
        }
    }
}

// ---- #9: classifier + cleanup (blocks 0-63 classify+zero own rows; all zero d_deg) ----
__global__ void k_cls_cleanup(const float* __restrict__ Wc, const float* __restrict__ bc,
                              float* __restrict__ out) {
    __shared__ float sm[DD];
    int b = blockIdx.x;
    int t = threadIdx.x;   // 256 threads
    if (b < NG) {
        if (t < DD) {
            float cnt = fmaxf((float)d_gcnt[b], 1.0f);
            sm[t] = d_gsum[b * DD + t] / cnt;
        }
        __syncthreads();
        if (t < NCLS) {
            float o = bc[t];
#pragma unroll 4
            for (int k = 0; k < DD; k++) o += sm[k] * Wc[k * NCLS + t];
            out[b * NCLS + t] = o;
        }
        // restore zero invariant for this graph's slots
        if (t < DD) d_gsum[b * DD + t] = 0.f;
        if (t == 0) d_gcnt[b] = 0;
    }
    int i = b * 256 + t;
    if (i < NN) d_deg[i] = 0;
    if (i == 0) d_total = 0;
}

// ---------------- launch ----------------
extern "C" void kernel_launch(void* const* d_in, const int* in_sizes, int n_in,
                              void* d_out, int out_size)
{
    const float* h   = (const float*)d_in[0];
    const int*   src = (const int*)d_in[1];
    const int*   dst = (const int*)d_in[2];
    const int*   gid = (const int*)d_in[3];
    int wb = (in_sizes[4] == 1) ? 5 : 4;
    const float* W1s = (const float*)d_in[wb + 0];
    const float* W1n = (const float*)d_in[wb + 1];
    const float* b1  = (const float*)d_in[wb + 2];
    const float* W2s = (const float*)d_in[wb + 3];
    const float* W2n = (const float*)d_in[wb + 4];
    const float* b2  = (const float*)d_in[wb + 5];
    const float* Wc  = (const float*)d_in[wb + 6];
    const float* bc  = (const float*)d_in[wb + 7];
    float* out = (float*)d_out;

    void *phb, *pnb, *px1, *pw;
    cudaGetSymbolAddress(&phb, d_hb);
    cudaGetSymbolAddress(&pnb, d_neighb);
    cudaGetSymbolAddress(&px1, d_x1b);
    cudaGetSymbolAddress(&pw, d_wimg);
    __half* hb = (__half*)phb;
    __half* nb = (__half*)pnb;
    __half* x1 = (__half*)px1;
    const uint4* wimg = (const uint4*)pw;

    cudaFuncSetAttribute(k_gemm_mma, cudaFuncAttributeMaxDynamicSharedMemorySize, SM_TOT);

    const int GB = (NN + 127) / 128;   // 782 tiles
    const uint4* B1 = wimg;            // each image = 4096 uint4
    const uint4* B2 = wimg + 4096;

    // #1: h conversion + degree/graph counting (counters zero at entry)
    k_cvth_count<<<(NN * DD / 8 + 255) / 256, 256>>>((const float4*)h, (uint4*)hb, dst, gid);
    // #2: one-shot scan (atomic ticket)
    k_scan_atomic<<<SNB, SBS>>>();
    // #3: scatter
    k_scatter<<<(NE + 255) / 256, 256>>>(src, dst);
    // #4: layer-1 aggregation  <-- ncu capture slot
    k_agg<<<NN / 8, 256>>>((const uint4*)hb);
    // #5: weight images
    k_cvtw<<<128, 256>>>(W1s, W1n, W2s, W2n);
    // #6: layer-1 GEMM (relu, store x1)
    k_gemm_mma<<<GB, 256, SM_TOT>>>((const uint4*)hb, (const uint4*)nb, B1, b1,
                                    (uint32_t*)x1, gid, 0);
    // #7: layer-2 aggregation
    k_agg<<<NN / 8, 256>>>((const uint4*)x1);
    // #8: layer-2 GEMM + fused graph pooling into d_gsum
    k_gemm_mma<<<GB, 256, SM_TOT>>>((const uint4*)x1, (const uint4*)nb, B2, b2,
                                    (uint32_t*)x1, gid, 1);
    // #9: classifier + zero-invariant restore
    k_cls_cleanup<<<(NN + 255) / 256, 256>>>(Wc, bc, out);
}